// round 1
// baseline (speedup 1.0000x reference)
#include <cuda_runtime.h>
#include <math.h>

#define SB   16          // batch
#define SS   2048        // sequence
#define SD   128         // head dim
#define BM   64          // query tile
#define BN   64          // key tile
#define NCHUNK 16        // suffix-sum chunks (SS / 128)

// Scratch (allocation-free rule: static __device__ arrays).
// g_SV[b][q][d] = sum_{k > q} V[b][k][d]
__device__ float g_SV[SB * SS * SD];
__device__ float g_T[SB * NCHUNK * SD];   // per-chunk V sums

// ---------------------------------------------------------------------------
// Pass 1: per-chunk totals of V (chunks of 128 rows)
// ---------------------------------------------------------------------------
__global__ void chunk_sum_kernel(const float* __restrict__ V) {
    int c = blockIdx.x;          // chunk 0..15
    int b = blockIdx.y;          // batch
    int d = threadIdx.x;         // 0..127
    const float* vp = V + ((b * SS + c * 128) * SD) + d;
    float acc = 0.f;
#pragma unroll 4
    for (int k = 0; k < 128; ++k) acc += vp[k * SD];
    g_T[(b * NCHUNK + c) * SD + d] = acc;
}

// ---------------------------------------------------------------------------
// Pass 2: suffix sums. carry = sum of later chunks, then local suffix scan.
// SV[k] excludes row k itself.
// ---------------------------------------------------------------------------
__global__ void suffix_kernel(const float* __restrict__ V) {
    int c = blockIdx.x;
    int b = blockIdx.y;
    int d = threadIdx.x;
    float acc = 0.f;
#pragma unroll
    for (int c2 = c + 1; c2 < NCHUNK; ++c2) acc += g_T[(b * NCHUNK + c2) * SD + d];
    const float* vp = V + ((b * SS + c * 128) * SD) + d;
    float*       sp = g_SV + ((b * SS + c * 128) * SD) + d;
    for (int k = 127; k >= 0; --k) {
        sp[k * SD] = acc;        // strictly-greater suffix
        acc += vp[k * SD];
    }
}

// ---------------------------------------------------------------------------
// Flash attention over the causal (lower-triangular) part, with the
// "masked entries are exact zeros in the softmax" correction in the epilogue.
//
// Smem layout (floats):
//   Qs [128][64]  transposed+swizzled  (8192)
//   Ks [128][64]  transposed+swizzled  (8192)
//   Vs [64][128]  row-major            (8192)
//   Ps [64][64]   probabilities        (4096)
//   row_alpha[64], row_m[64], row_l[64]
// Total = 28864 floats = 115456 B  -> 2 blocks/SM (226 KB)
// ---------------------------------------------------------------------------
#define SMEM_FLOATS (8192 * 3 + 4096 + 192)
#define SMEM_BYTES  (SMEM_FLOATS * 4)

__global__ __launch_bounds__(256, 2)
void flash_kernel(const float* __restrict__ Q, const float* __restrict__ K,
                  const float* __restrict__ V, float* __restrict__ O) {
    extern __shared__ __align__(16) float smem[];
    float* Qs = smem;                       // [d][64] swizzled
    float* Ks = Qs + 8192;                  // [d][64] swizzled
    float* Vs = Ks + 8192;                  // [k][128]
    float* Ps = Vs + 8192;                  // [row][64]
    float* row_alpha = Ps + 4096;
    float* row_m     = row_alpha + 64;
    float* row_l     = row_m + 64;

    const int tid   = threadIdx.x;
    const int b     = blockIdx.y;
    const int qtile = (gridDim.x - 1) - blockIdx.x;   // heavy tiles first

    // QK-phase mapping: 16x16 grid, 4x4 score microtile
    const int ty = tid >> 4;      // 0..15 -> rows ty*4..+3
    const int tx = tid & 15;      // 0..15 -> cols tx*4..+3
    // PV-phase mapping: 8x32 grid, 8 rows x 4 dims
    const int tyv = tid >> 5;     // 0..7  -> rows tyv*8..+7
    const int txv = tid & 31;     // 0..31 -> dims txv*4..+3

    const float scale = 0.08838834764831845f;   // 1/sqrt(128)

    // ---- Load Q tile (transposed + swizzled) ----
    {
        const float4* Qg = (const float4*)(Q + (b * SS + qtile * BM) * SD);
#pragma unroll
        for (int i = 0; i < 8; ++i) {
            int f   = i * 256 + tid;
            int row = f >> 5;            // 0..63 (query row in tile)
            int d4  = f & 31;            // float4 index along d
            float4 v = Qg[row * 32 + d4];
            int c4   = (row >> 2) ^ (d4 & 15);
            int base = d4 * 4 * 64 + c4 * 4 + (row & 3);
            Qs[base]       = v.x;
            Qs[base + 64]  = v.y;
            Qs[base + 128] = v.z;
            Qs[base + 192] = v.w;
        }
    }

    float m_i[4], l_i[4];
#pragma unroll
    for (int i = 0; i < 4; ++i) { m_i[i] = -1e30f; l_i[i] = 0.f; }
    float acc[8][4];
#pragma unroll
    for (int r = 0; r < 8; ++r)
#pragma unroll
        for (int c = 0; c < 4; ++c) acc[r][c] = 0.f;

    const int nkt = qtile + 1;
    for (int kt = 0; kt < nkt; ++kt) {
        __syncthreads();   // previous PV done reading Vs/Ps

        // ---- Load K (transposed+swizzled) and V (row-major) tiles ----
        {
            const float4* Kg = (const float4*)(K + (b * SS + kt * BN) * SD);
            const float4* Vg = (const float4*)(V + (b * SS + kt * BN) * SD);
#pragma unroll
            for (int i = 0; i < 8; ++i) {
                int f   = i * 256 + tid;
                int row = f >> 5;
                int d4  = f & 31;
                float4 kv = Kg[row * 32 + d4];
                int c4    = (row >> 2) ^ (d4 & 15);
                int base  = d4 * 4 * 64 + c4 * 4 + (row & 3);
                Ks[base]       = kv.x;
                Ks[base + 64]  = kv.y;
                Ks[base + 128] = kv.z;
                Ks[base + 192] = kv.w;
                ((float4*)Vs)[row * 32 + d4] = Vg[row * 32 + d4];
            }
        }
        __syncthreads();

        // ---- QK^T: s[4][4] over d=0..127 ----
        float s[4][4];
#pragma unroll
        for (int i = 0; i < 4; ++i)
#pragma unroll
            for (int j = 0; j < 4; ++j) s[i][j] = 0.f;

        const float4* Qs4 = (const float4*)Qs;
        const float4* Ks4 = (const float4*)Ks;
#pragma unroll 4
        for (int dg = 0; dg < 32; ++dg) {
            int sw = dg & 15;
            int cq = ty ^ sw;
            int ck = tx ^ sw;
#pragma unroll
            for (int jj = 0; jj < 4; ++jj) {
                int d = dg * 4 + jj;
                float4 q4 = Qs4[d * 16 + cq];
                float4 k4 = Ks4[d * 16 + ck];
                float qf[4] = {q4.x, q4.y, q4.z, q4.w};
                float kf[4] = {k4.x, k4.y, k4.z, k4.w};
#pragma unroll
                for (int i = 0; i < 4; ++i)
#pragma unroll
                    for (int j = 0; j < 4; ++j)
                        s[i][j] += qf[i] * kf[j];
            }
        }

        // ---- Online softmax (rows ty*4..+3, 16 lanes per row group) ----
        const int  grow0 = qtile * BM + ty * 4;
        const int  gcol0 = kt * BN + tx * 4;
        const bool diag  = (kt == qtile);
#pragma unroll
        for (int i = 0; i < 4; ++i) {
            int grow = grow0 + i;
            float sv[4];
            float tm = -1e30f;
#pragma unroll
            for (int j = 0; j < 4; ++j) {
                float x = s[i][j] * scale;
                if (diag && (gcol0 + j > grow)) x = -1e30f;
                sv[j] = x;
                tm = fmaxf(tm, x);
            }
            tm = fmaxf(tm, __shfl_xor_sync(0xffffffffu, tm, 1));
            tm = fmaxf(tm, __shfl_xor_sync(0xffffffffu, tm, 2));
            tm = fmaxf(tm, __shfl_xor_sync(0xffffffffu, tm, 4));
            tm = fmaxf(tm, __shfl_xor_sync(0xffffffffu, tm, 8));

            float mn = fmaxf(m_i[i], tm);
            float al = __expf(m_i[i] - mn);
            float p[4];
            float rs = 0.f;
#pragma unroll
            for (int j = 0; j < 4; ++j) { p[j] = __expf(sv[j] - mn); rs += p[j]; }
            rs += __shfl_xor_sync(0xffffffffu, rs, 1);
            rs += __shfl_xor_sync(0xffffffffu, rs, 2);
            rs += __shfl_xor_sync(0xffffffffu, rs, 4);
            rs += __shfl_xor_sync(0xffffffffu, rs, 8);

            l_i[i] = l_i[i] * al + rs;
            m_i[i] = mn;
            if (tx == 0) row_alpha[ty * 4 + i] = al;
            *((float4*)&Ps[(ty * 4 + i) * 64 + tx * 4]) = make_float4(p[0], p[1], p[2], p[3]);
        }
        __syncthreads();   // Ps + row_alpha ready

        // ---- PV: acc = acc*alpha + P @ V ----
#pragma unroll
        for (int r = 0; r < 8; ++r) {
            float a = row_alpha[tyv * 8 + r];
            acc[r][0] *= a; acc[r][1] *= a; acc[r][2] *= a; acc[r][3] *= a;
        }
        const float4* Vs4 = (const float4*)Vs;
#pragma unroll 2
        for (int k = 0; k < 64; ++k) {
            float4 v4 = Vs4[k * 32 + txv];
#pragma unroll
            for (int r = 0; r < 8; ++r) {
                float pr = Ps[(tyv * 8 + r) * 64 + k];
                acc[r][0] += pr * v4.x;
                acc[r][1] += pr * v4.y;
                acc[r][2] += pr * v4.z;
                acc[r][3] += pr * v4.w;
            }
        }
    }

    // publish per-row stats for the PV-mapped epilogue
    if (tx == 0) {
#pragma unroll
        for (int i = 0; i < 4; ++i) {
            row_m[ty * 4 + i] = m_i[i];
            row_l[ty * 4 + i] = l_i[i];
        }
    }
    __syncthreads();

    // ---- Epilogue: masked-zeros correction + normalize + store ----
    const float4* SV4 = (const float4*)g_SV;
    float4*       O4  = (float4*)O;
#pragma unroll
    for (int r = 0; r < 8; ++r) {
        int lrow = tyv * 8 + r;
        int grow = qtile * BM + lrow;
        float m = row_m[lrow];
        float l = row_l[lrow];
        float a0 = acc[r][0], a1 = acc[r][1], a2 = acc[r][2], a3 = acc[r][3];
        float cnt = (float)(SS - 1 - grow);
        if (cnt > 0.f) {
            float mn = fmaxf(m, 0.f);
            float e  = __expf(m - mn);     // rescale existing acc/l
            float em = __expf(-mn);        // weight of each masked (score=0) entry
            float4 sv = SV4[(b * SS + grow) * 32 + txv];
            a0 = a0 * e + em * sv.x;
            a1 = a1 * e + em * sv.y;
            a2 = a2 * e + em * sv.z;
            a3 = a3 * e + em * sv.w;
            l  = l * e + cnt * em;
        }
        float inv = 1.0f / l;
        O4[(b * SS + grow) * 32 + txv] = make_float4(a0 * inv, a1 * inv, a2 * inv, a3 * inv);
    }
}

// ---------------------------------------------------------------------------
extern "C" void kernel_launch(void* const* d_in, const int* in_sizes, int n_in,
                              void* d_out, int out_size) {
    const float* Q = (const float*)d_in[0];
    const float* K = (const float*)d_in[1];
    const float* V = (const float*)d_in[2];
    float*       O = (float*)d_out;

    cudaFuncSetAttribute(flash_kernel,
                         cudaFuncAttributeMaxDynamicSharedMemorySize, SMEM_BYTES);

    chunk_sum_kernel<<<dim3(NCHUNK, SB), 128>>>(V);
    suffix_kernel   <<<dim3(NCHUNK, SB), 128>>>(V);
    flash_kernel    <<<dim3(SS / BM, SB), 256, SMEM_BYTES>>>(Q, K, V, O);
}

// round 3
// speedup vs baseline: 1.6759x; 1.6759x over previous
#include <cuda_runtime.h>
#include <math.h>

#define SB   16
#define SS   2048
#define SD   128
#define BM   64
#define BN   64
#define NCH  64          // suffix chunks
#define CROWS 32         // rows per chunk

// scratch: SV[b][q][d] = sum_{k>q} V[b][k][d]
__device__ float g_SV[SB * SS * SD];
__device__ float g_T[SB * NCH * SD];

// ---------------------------------------------------------------------------
__global__ void chunk_sum_kernel(const float* __restrict__ V) {
    int c = blockIdx.x, b = blockIdx.y, d = threadIdx.x;
    const float* vp = V + ((b * SS + c * CROWS) * SD) + d;
    float acc = 0.f;
#pragma unroll
    for (int k = 0; k < CROWS; ++k) acc += vp[k * SD];
    g_T[(b * NCH + c) * SD + d] = acc;
}

__global__ void suffix_kernel(const float* __restrict__ V) {
    int c = blockIdx.x, b = blockIdx.y, d = threadIdx.x;
    float acc = 0.f;
    for (int c2 = c + 1; c2 < NCH; ++c2) acc += g_T[(b * NCH + c2) * SD + d];
    const float* vp = V + ((b * SS + c * CROWS) * SD) + d;
    float*       sp = g_SV + ((b * SS + c * CROWS) * SD) + d;
#pragma unroll
    for (int k = CROWS - 1; k >= 0; --k) { sp[k * SD] = acc; acc += vp[k * SD]; }
}

// ---------------------------------------------------------------------------
__device__ __forceinline__ unsigned f2tf(float x) {
    unsigned r; asm("cvt.rna.tf32.f32 %0, %1;" : "=r"(r) : "f"(x)); return r;
}
__device__ __forceinline__ void mma8(float c[4], unsigned a0, unsigned a1,
                                     unsigned a2, unsigned a3,
                                     unsigned b0, unsigned b1) {
    asm volatile(
        "mma.sync.aligned.m16n8k8.row.col.f32.tf32.tf32.f32 "
        "{%0,%1,%2,%3}, {%4,%5,%6,%7}, {%8,%9}, {%0,%1,%2,%3};"
        : "+f"(c[0]), "+f"(c[1]), "+f"(c[2]), "+f"(c[3])
        : "r"(a0), "r"(a1), "r"(a2), "r"(a3), "r"(b0), "r"(b1));
}

// smem: Ks [64][128] tf32, float4-xor swizzle   (8192 f)
//       Vs [64][128] tf32, additive swizzle     (8192 f)  (also Q staging)
//       Ps [64][64]  tf32, float2-xor swizzle   (4096 f)
#define SMEM_BYTES ((8192 + 8192 + 4096) * 4)

__global__ __launch_bounds__(128)
void flash_kernel(const float* __restrict__ Q, const float* __restrict__ K,
                  const float* __restrict__ V, float* __restrict__ O) {
    extern __shared__ __align__(16) float smem[];
    float* Ks = smem;
    float* Vs = Ks + 8192;
    float* Ps = Vs + 8192;

    const int tid  = threadIdx.x;
    const int w    = tid >> 5;
    const int lane = tid & 31;
    const int g    = lane >> 2;     // 0..7
    const int m_   = lane & 3;      // 0..3
    const int b    = blockIdx.y;
    const int qtile = (gridDim.x - 1) - blockIdx.x;   // heavy-first
    const int R    = w * 16 + g;    // local row (R and R+8 owned by this thread)

    const float SCALE2 = 0.12751744f;   // log2(e)/sqrt(128)

    // ---- stage Q into Vs, then pull fragments into registers ----
    {
        const float4* Qg  = (const float4*)(Q + (b * SS + qtile * BM) * SD);
        float4*       Vs4 = (float4*)Vs;
#pragma unroll
        for (int i = 0; i < 16; ++i) Vs4[i * 128 + tid] = Qg[i * 128 + tid];
    }
    __syncthreads();
    float qa[2][32];
#pragma unroll
    for (int t = 0; t < 32; ++t) {
        qa[0][t] = Vs[R * 128 + t * 4 + m_];
        qa[1][t] = Vs[(R + 8) * 128 + t * 4 + m_];
    }

    float m1 = -1e30f, m2 = -1e30f, l1 = 0.f, l2 = 0.f;
    float acc[16][4];
#pragma unroll
    for (int nd = 0; nd < 16; ++nd)
#pragma unroll
        for (int e = 0; e < 4; ++e) acc[nd][e] = 0.f;

    // V-read offsets (constant across tiles): addr = k*128 + yv[nd] (+512 for b1)
    int yv[16];
    {
        int g2 = g >> 2;
#pragma unroll
        for (int nd = 0; nd < 16; ++nd) {
            int d4 = nd * 2 + g2;
            yv[nd] = m_ * 128 + 4 * ((d4 & 24) | ((d4 + 2 * m_) & 7)) + (g & 3);
        }
    }
    const int baseK = g * 128 + m_;
    const int sw4   = 4 * g;        // P swizzle (R&7 == g)

    for (int kt = 0; kt <= qtile; ++kt) {
        __syncthreads();
        // ---- load K (xor swizzle) and V (additive swizzle), tf32-rounded ----
        {
            const float4* Kg  = (const float4*)(K + (b * SS + kt * BN) * SD);
            const float4* Vg  = (const float4*)(V + (b * SS + kt * BN) * SD);
            float4* Ks4 = (float4*)Ks;
            float4* Vs4 = (float4*)Vs;
#pragma unroll
            for (int i = 0; i < 16; ++i) {
                int f = i * 128 + tid;
                int n = f >> 5, k4 = f & 31;
                float4 kv = Kg[f];
                float4 kr;
                kr.x = __uint_as_float(f2tf(kv.x));
                kr.y = __uint_as_float(f2tf(kv.y));
                kr.z = __uint_as_float(f2tf(kv.z));
                kr.w = __uint_as_float(f2tf(kv.w));
                Ks4[n * 32 + (k4 ^ (n & 7))] = kr;
                float4 vv = Vg[f];
                float4 vr;
                vr.x = __uint_as_float(f2tf(vv.x));
                vr.y = __uint_as_float(f2tf(vv.y));
                vr.z = __uint_as_float(f2tf(vv.z));
                vr.w = __uint_as_float(f2tf(vv.w));
                Vs4[n * 32 + ((k4 & 24) | ((k4 + 2 * (n & 7)) & 7))] = vr;
            }
        }
        __syncthreads();

        // ---- QK^T (2-split tf32) ----
        float sacc[8][4];
#pragma unroll
        for (int nb = 0; nb < 8; ++nb)
#pragma unroll
            for (int e = 0; e < 4; ++e) sacc[nb][e] = 0.f;

        const unsigned* Ku = (const unsigned*)Ks;
#pragma unroll
        for (int ks = 0; ks < 16; ++ks) {
            float q00 = qa[0][2 * ks],     q10 = qa[1][2 * ks];
            float q01 = qa[0][2 * ks + 1], q11 = qa[1][2 * ks + 1];
            unsigned ah0 = f2tf(q00), ah1 = f2tf(q10);
            unsigned ah2 = f2tf(q01), ah3 = f2tf(q11);
            unsigned al0 = f2tf(q00 - __uint_as_float(ah0));
            unsigned al1 = f2tf(q10 - __uint_as_float(ah1));
            unsigned al2 = f2tf(q01 - __uint_as_float(ah2));
            unsigned al3 = f2tf(q11 - __uint_as_float(ah3));
            int xk0 = 4 * ((2 * ks) ^ g);
            int xk1 = 4 * ((2 * ks + 1) ^ g);
#pragma unroll
            for (int nb = 0; nb < 8; ++nb) {
                unsigned b0 = Ku[nb * 1024 + baseK + xk0];
                unsigned b1 = Ku[nb * 1024 + baseK + xk1];
                mma8(sacc[nb], ah0, ah1, ah2, ah3, b0, b1);
                mma8(sacc[nb], al0, al1, al2, al3, b0, b1);
            }
        }

        // ---- online softmax (rows R, R+8; 4 lanes per row) ----
        const bool diag = (kt == qtile);
        const int grow1 = qtile * 64 + R;
        const int grow2 = grow1 + 8;
        float tm1 = -1e30f, tm2 = -1e30f;
#pragma unroll
        for (int nb = 0; nb < 8; ++nb) {
            int gc = kt * 64 + nb * 8 + 2 * m_;
            float x0 = sacc[nb][0] * SCALE2; if (diag && gc     > grow1) x0 = -1e30f;
            float x1 = sacc[nb][1] * SCALE2; if (diag && gc + 1 > grow1) x1 = -1e30f;
            float x2 = sacc[nb][2] * SCALE2; if (diag && gc     > grow2) x2 = -1e30f;
            float x3 = sacc[nb][3] * SCALE2; if (diag && gc + 1 > grow2) x3 = -1e30f;
            sacc[nb][0] = x0; sacc[nb][1] = x1; sacc[nb][2] = x2; sacc[nb][3] = x3;
            tm1 = fmaxf(tm1, fmaxf(x0, x1));
            tm2 = fmaxf(tm2, fmaxf(x2, x3));
        }
        tm1 = fmaxf(tm1, __shfl_xor_sync(0xffffffffu, tm1, 1));
        tm1 = fmaxf(tm1, __shfl_xor_sync(0xffffffffu, tm1, 2));
        tm2 = fmaxf(tm2, __shfl_xor_sync(0xffffffffu, tm2, 1));
        tm2 = fmaxf(tm2, __shfl_xor_sync(0xffffffffu, tm2, 2));

        float mn1 = fmaxf(m1, tm1), mn2 = fmaxf(m2, tm2);
        float al1f = exp2f(m1 - mn1), al2f = exp2f(m2 - mn2);
        m1 = mn1; m2 = mn2;

        float rs1 = 0.f, rs2 = 0.f;
        float2* Ps2 = (float2*)Ps;
#pragma unroll
        for (int nb = 0; nb < 8; ++nb) {
            float p0 = exp2f(sacc[nb][0] - mn1);
            float p1 = exp2f(sacc[nb][1] - mn1);
            float p2 = exp2f(sacc[nb][2] - mn2);
            float p3 = exp2f(sacc[nb][3] - mn2);
            float r0 = __uint_as_float(f2tf(p0));
            float r1 = __uint_as_float(f2tf(p1));
            float r2 = __uint_as_float(f2tf(p2));
            float r3 = __uint_as_float(f2tf(p3));
            rs1 += r0 + r1; rs2 += r2 + r3;
            int c2x = (m_ + 4 * nb) ^ sw4;
            Ps2[R * 32 + c2x]       = make_float2(r0, r1);
            Ps2[(R + 8) * 32 + c2x] = make_float2(r2, r3);
        }
        rs1 += __shfl_xor_sync(0xffffffffu, rs1, 1);
        rs1 += __shfl_xor_sync(0xffffffffu, rs1, 2);
        rs2 += __shfl_xor_sync(0xffffffffu, rs2, 1);
        rs2 += __shfl_xor_sync(0xffffffffu, rs2, 2);
        l1 = l1 * al1f + rs1;
        l2 = l2 * al2f + rs2;
        __syncwarp();   // P rows for this warp are self-written; warp-local sync only

        // ---- P @ V ----
#pragma unroll
        for (int nd = 0; nd < 16; ++nd) {
            acc[nd][0] *= al1f; acc[nd][1] *= al1f;
            acc[nd][2] *= al2f; acc[nd][3] *= al2f;
        }
        const unsigned* Pu = (const unsigned*)Ps;
        const unsigned* Vu = (const unsigned*)Vs;
#pragma unroll
        for (int ks = 0; ks < 8; ++ks) {
            int c2a = (ks * 4 + (m_ >> 1)) ^ sw4;
            int c2b = (ks * 4 + (m_ >> 1) + 2) ^ sw4;
            unsigned a0 = Pu[R * 64 + 2 * c2a + (m_ & 1)];
            unsigned a1 = Pu[(R + 8) * 64 + 2 * c2a + (m_ & 1)];
            unsigned a2 = Pu[R * 64 + 2 * c2b + (m_ & 1)];
            unsigned a3 = Pu[(R + 8) * 64 + 2 * c2b + (m_ & 1)];
#pragma unroll
            for (int nd = 0; nd < 16; ++nd) {
                unsigned b0 = Vu[ks * 1024 + yv[nd]];
                unsigned b1 = Vu[ks * 1024 + 512 + yv[nd]];
                mma8(acc[nd], a0, a1, a2, a3, b0, b1);
            }
        }
    }

    // ---- epilogue: masked-zeros correction + normalize + store ----
    const float2* SV2 = (const float2*)g_SV;
    float2*       O2  = (float2*)O;
#pragma unroll
    for (int h = 0; h < 2; ++h) {
        int grow = qtile * 64 + R + 8 * h;
        float mm = h ? m2 : m1;
        float ll = h ? l2 : l1;
        long base = (long)(b * SS + grow) * 64;
        float cnt = (float)(SS - 1 - grow);
        float e = 1.f, em = 0.f;
        if (cnt > 0.f) {
            float mn = fmaxf(mm, 0.f);
            e  = exp2f(mm - mn);
            em = exp2f(-mn);
            ll = ll * e + cnt * em;
        }
        float inv = 1.0f / ll;
#pragma unroll
        for (int nd = 0; nd < 16; ++nd) {
            float o0 = acc[nd][2 * h + 0];
            float o1 = acc[nd][2 * h + 1];
            if (cnt > 0.f) {
                float2 sv = SV2[base + nd * 4 + m_];
                o0 = o0 * e + em * sv.x;
                o1 = o1 * e + em * sv.y;
            }
            O2[base + nd * 4 + m_] = make_float2(o0 * inv, o1 * inv);
        }
    }
}

// ---------------------------------------------------------------------------
extern "C" void kernel_launch(void* const* d_in, const int* in_sizes, int n_in,
                              void* d_out, int out_size) {
    const float* Q = (const float*)d_in[0];
    const float* K = (const float*)d_in[1];
    const float* V = (const float*)d_in[2];
    float*       O = (float*)d_out;

    cudaFuncSetAttribute(flash_kernel,
                         cudaFuncAttributeMaxDynamicSharedMemorySize, SMEM_BYTES);

    chunk_sum_kernel<<<dim3(NCH, SB), 128>>>(V);
    suffix_kernel   <<<dim3(NCH, SB), 128>>>(V);
    flash_kernel    <<<dim3(SS / BM, SB), 128, SMEM_BYTES>>>(Q, K, V, O);
}

// round 6
// speedup vs baseline: 3.7248x; 2.2226x over previous
#include <cuda_runtime.h>
#include <math.h>
#include <stdint.h>

#define SB   16
#define SS   2048
#define SD   128
#define BM   128
#define BN   64
#define NCH  64
#define CROWS 32

// scratch: SV[b][q][d] = sum_{k>q} V[b][k][d]
__device__ float g_SV[SB * SS * SD];
__device__ float g_T[SB * NCH * SD];

// ---------------------------------------------------------------------------
__global__ void chunk_sum_kernel(const float* __restrict__ V) {
    int c = blockIdx.x, b = blockIdx.y, d = threadIdx.x;
    const float* vp = V + ((b * SS + c * CROWS) * SD) + d;
    float acc = 0.f;
#pragma unroll
    for (int k = 0; k < CROWS; ++k) acc += vp[k * SD];
    g_T[(b * NCH + c) * SD + d] = acc;
}

__global__ void suffix_kernel(const float* __restrict__ V) {
    int c = blockIdx.x, b = blockIdx.y, d = threadIdx.x;
    float acc = 0.f;
    for (int c2 = c + 1; c2 < NCH; ++c2) acc += g_T[(b * NCH + c2) * SD + d];
    const float* vp = V + ((b * SS + c * CROWS) * SD) + d;
    float*       sp = g_SV + ((b * SS + c * CROWS) * SD) + d;
#pragma unroll
    for (int k = CROWS - 1; k >= 0; --k) { sp[k * SD] = acc; acc += vp[k * SD]; }
}

// ---------------------------------------------------------------------------
__device__ __forceinline__ unsigned f2tf(float x) {            // rna round (Q split)
    unsigned r; asm("cvt.rna.tf32.f32 %0, %1;" : "=r"(r) : "f"(x)); return r;
}
__device__ __forceinline__ float ftrunc_tf(float x) {          // HW-matching truncation
    return __uint_as_float(__float_as_uint(x) & 0xffffe000u);
}
__device__ __forceinline__ float ex2(float x) {
    float r; asm("ex2.approx.f32 %0, %1;" : "=f"(r) : "f"(x)); return r;
}
__device__ __forceinline__ void mma8(float c[4], unsigned a0, unsigned a1,
                                     unsigned a2, unsigned a3,
                                     unsigned b0, unsigned b1) {
    asm volatile(
        "mma.sync.aligned.m16n8k8.row.col.f32.tf32.tf32.f32 "
        "{%0,%1,%2,%3}, {%4,%5,%6,%7}, {%8,%9}, {%0,%1,%2,%3};"
        : "+f"(c[0]), "+f"(c[1]), "+f"(c[2]), "+f"(c[3])
        : "r"(a0), "r"(a1), "r"(a2), "r"(a3), "r"(b0), "r"(b1));
}
__device__ __forceinline__ void cp16(uint32_t dst, const void* src) {
    asm volatile("cp.async.cg.shared.global [%0], [%1], 16;" :: "r"(dst), "l"(src));
}

// smem floats: K0[8192] V0[8192] K1[8192] V1[8192] Ps[8192]  = 40960 f = 160 KB
#define OFF_K0 0
#define OFF_V0 8192
#define OFF_K1 16384
#define OFF_V1 24576
#define OFF_P  32768
#define SMEM_BYTES (40960 * 4)

__global__ __launch_bounds__(256, 1)
void flash_kernel(const float* __restrict__ Q, const float* __restrict__ K,
                  const float* __restrict__ V, float* __restrict__ O) {
    extern __shared__ __align__(16) float smem[];
    const uint32_t sbase = (uint32_t)__cvta_generic_to_shared(smem);

    const int tid  = threadIdx.x;
    const int w    = tid >> 5;       // 0..7
    const int lane = tid & 31;
    const int g    = lane >> 2;      // 0..7
    const int m_   = lane & 3;       // 0..3
    const int b    = blockIdx.x;                       // batch on x
    const int qtile = (gridDim.y - 1) - blockIdx.y;    // heavy tiles launch first
    const int R    = w * 16 + g;     // local rows R and R+8 (0..127)

    const float SCALE2 = 0.12751744f;   // log2(e)/sqrt(128)

    // ---- Q fragments straight from gmem (one-time) ----
    float qa[2][32];
    {
        const float* Qr0 = Q + (size_t)(b * SS + qtile * BM + R) * SD + m_;
        const float* Qr1 = Qr0 + 8 * SD;
#pragma unroll
        for (int t = 0; t < 32; ++t) {
            qa[0][t] = Qr0[t * 4];
            qa[1][t] = Qr1[t * 4];
        }
    }

    float m1 = -1e30f, m2 = -1e30f, l1 = 0.f, l2 = 0.f;
    float acc[16][4];
#pragma unroll
    for (int nd = 0; nd < 16; ++nd)
#pragma unroll
        for (int e = 0; e < 4; ++e) acc[nd][e] = 0.f;

    // V-read float offsets (constant): addr = ks*1024 + yv[nd] (+512 for b1)
    int yv[16];
    {
        int g2 = g >> 2;
#pragma unroll
        for (int nd = 0; nd < 16; ++nd) {
            int d4 = nd * 2 + g2;
            yv[nd] = m_ * 128 + 4 * ((d4 & 24) | ((d4 + 2 * m_) & 7)) + (g & 3);
        }
    }
    const int baseK = g * 128 + m_;
    const int sw4   = 4 * g;         // P swizzle key (R&7 == g)

    // BM=128, BN=64: rows qtile*128..qtile*128+127 need kv tiles 0..(2*qtile+1)
    const int nkt = 2 * qtile + 2;

    // ---- issue tile 0 ----
    {
        const float4* Kg = (const float4*)(K + (size_t)(b * SS) * SD);
        const float4* Vg = (const float4*)(V + (size_t)(b * SS) * SD);
#pragma unroll
        for (int i = 0; i < 8; ++i) {
            int f = i * 256 + tid;
            int n = f >> 5, k4 = f & 31;
            cp16(sbase + (OFF_K0 + n * 128 + (k4 ^ (n & 7)) * 4) * 4, Kg + f);
            cp16(sbase + (OFF_V0 + n * 128 + ((k4 & 24) | ((k4 + 2 * (n & 7)) & 7)) * 4) * 4, Vg + f);
        }
        asm volatile("cp.async.commit_group;" ::: "memory");
    }

    for (int kt = 0; kt < nkt; ++kt) {
        const bool has_next = (kt + 1 < nkt);
        if (has_next) {   // stream next tile into the other buffer
            const float4* Kg = (const float4*)(K + (size_t)(b * SS + (kt + 1) * BN) * SD);
            const float4* Vg = (const float4*)(V + (size_t)(b * SS + (kt + 1) * BN) * SD);
            const int ob = ((kt + 1) & 1) ? OFF_K1 : OFF_K0;
#pragma unroll
            for (int i = 0; i < 8; ++i) {
                int f = i * 256 + tid;
                int n = f >> 5, k4 = f & 31;
                cp16(sbase + (ob + n * 128 + (k4 ^ (n & 7)) * 4) * 4, Kg + f);
                cp16(sbase + (ob + 8192 + n * 128 + ((k4 & 24) | ((k4 + 2 * (n & 7)) & 7)) * 4) * 4, Vg + f);
            }
            asm volatile("cp.async.commit_group;" ::: "memory");
            asm volatile("cp.async.wait_group 1;" ::: "memory");
        } else {
            asm volatile("cp.async.wait_group 0;" ::: "memory");
        }
        __syncthreads();   // tile kt visible to all warps

        const float* Kb = smem + ((kt & 1) ? OFF_K1 : OFF_K0);
        const float* Vb = Kb + 8192;

        // ---- QK^T (Q 2-split rna; K HW-truncated) ----
        float sacc[8][4];
#pragma unroll
        for (int nb = 0; nb < 8; ++nb)
#pragma unroll
            for (int e = 0; e < 4; ++e) sacc[nb][e] = 0.f;

        const unsigned* Ku = (const unsigned*)Kb;
#pragma unroll
        for (int ks = 0; ks < 16; ++ks) {
            float q00 = qa[0][2 * ks],     q10 = qa[1][2 * ks];
            float q01 = qa[0][2 * ks + 1], q11 = qa[1][2 * ks + 1];
            unsigned ah0 = f2tf(q00), ah1 = f2tf(q10);
            unsigned ah2 = f2tf(q01), ah3 = f2tf(q11);
            unsigned al0 = f2tf(q00 - __uint_as_float(ah0));
            unsigned al1 = f2tf(q10 - __uint_as_float(ah1));
            unsigned al2 = f2tf(q01 - __uint_as_float(ah2));
            unsigned al3 = f2tf(q11 - __uint_as_float(ah3));
            int xk0 = 4 * ((2 * ks) ^ g);
            int xk1 = 4 * ((2 * ks + 1) ^ g);
#pragma unroll
            for (int nb = 0; nb < 8; ++nb) {
                unsigned b0 = Ku[nb * 1024 + baseK + xk0];
                unsigned b1 = Ku[nb * 1024 + baseK + xk1];
                mma8(sacc[nb], ah0, ah1, ah2, ah3, b0, b1);
                mma8(sacc[nb], al0, al1, al2, al3, b0, b1);
            }
        }

        // ---- online softmax (rows R, R+8); per-element causal mask ----
        const int grow1 = qtile * BM + R;
        const int grow2 = grow1 + 8;
        float tm1 = -1e30f, tm2 = -1e30f;
#pragma unroll
        for (int nb = 0; nb < 8; ++nb) {
            int gc = kt * BN + nb * 8 + 2 * m_;
            float x0 = sacc[nb][0] * SCALE2; if (gc     > grow1) x0 = -1e30f;
            float x1 = sacc[nb][1] * SCALE2; if (gc + 1 > grow1) x1 = -1e30f;
            float x2 = sacc[nb][2] * SCALE2; if (gc     > grow2) x2 = -1e30f;
            float x3 = sacc[nb][3] * SCALE2; if (gc + 1 > grow2) x3 = -1e30f;
            sacc[nb][0] = x0; sacc[nb][1] = x1; sacc[nb][2] = x2; sacc[nb][3] = x3;
            tm1 = fmaxf(tm1, fmaxf(x0, x1));
            tm2 = fmaxf(tm2, fmaxf(x2, x3));
        }
        tm1 = fmaxf(tm1, __shfl_xor_sync(0xffffffffu, tm1, 1));
        tm1 = fmaxf(tm1, __shfl_xor_sync(0xffffffffu, tm1, 2));
        tm2 = fmaxf(tm2, __shfl_xor_sync(0xffffffffu, tm2, 1));
        tm2 = fmaxf(tm2, __shfl_xor_sync(0xffffffffu, tm2, 2));

        float mn1 = fmaxf(m1, tm1), mn2 = fmaxf(m2, tm2);
        float al1f = ex2(m1 - mn1), al2f = ex2(m2 - mn2);
        m1 = mn1; m2 = mn2;

        float rs1 = 0.f, rs2 = 0.f;
        float2* Ps2 = (float2*)(smem + OFF_P);
#pragma unroll
        for (int nb = 0; nb < 8; ++nb) {
            float r0 = ftrunc_tf(ex2(sacc[nb][0] - mn1));
            float r1 = ftrunc_tf(ex2(sacc[nb][1] - mn1));
            float r2 = ftrunc_tf(ex2(sacc[nb][2] - mn2));
            float r3 = ftrunc_tf(ex2(sacc[nb][3] - mn2));
            rs1 += r0 + r1; rs2 += r2 + r3;
            int c2x = (m_ + 4 * nb) ^ sw4;
            Ps2[R * 32 + c2x]       = make_float2(r0, r1);
            Ps2[(R + 8) * 32 + c2x] = make_float2(r2, r3);
        }
        rs1 += __shfl_xor_sync(0xffffffffu, rs1, 1);
        rs1 += __shfl_xor_sync(0xffffffffu, rs1, 2);
        rs2 += __shfl_xor_sync(0xffffffffu, rs2, 1);
        rs2 += __shfl_xor_sync(0xffffffffu, rs2, 2);
        l1 = l1 * al1f + rs1;
        l2 = l2 * al2f + rs2;
        __syncwarp();   // P rows are warp-local

        // ---- P @ V ----
#pragma unroll
        for (int nd = 0; nd < 16; ++nd) {
            acc[nd][0] *= al1f; acc[nd][1] *= al1f;
            acc[nd][2] *= al2f; acc[nd][3] *= al2f;
        }
        const unsigned* Pu = (const unsigned*)(smem + OFF_P);
        const unsigned* Vu = (const unsigned*)Vb;
#pragma unroll
        for (int ks = 0; ks < 8; ++ks) {
            int c2a = (ks * 4 + (m_ >> 1)) ^ sw4;
            int c2b = (ks * 4 + (m_ >> 1) + 2) ^ sw4;
            unsigned a0 = Pu[R * 64 + 2 * c2a + (m_ & 1)];
            unsigned a1 = Pu[(R + 8) * 64 + 2 * c2a + (m_ & 1)];
            unsigned a2 = Pu[R * 64 + 2 * c2b + (m_ & 1)];
            unsigned a3 = Pu[(R + 8) * 64 + 2 * c2b + (m_ & 1)];
#pragma unroll
            for (int nd = 0; nd < 16; ++nd) {
                unsigned b0 = Vu[ks * 1024 + yv[nd]];
                unsigned b1 = Vu[ks * 1024 + 512 + yv[nd]];
                mma8(acc[nd], a0, a1, a2, a3, b0, b1);
            }
        }
        __syncthreads();   // done reading this buffer before it is re-filled
    }

    // ---- epilogue: masked-zeros correction + normalize + store ----
    const float2* SV2 = (const float2*)g_SV;
    float2*       O2  = (float2*)O;
#pragma unroll
    for (int h = 0; h < 2; ++h) {
        int grow = qtile * BM + R + 8 * h;
        float mm = h ? m2 : m1;
        float ll = h ? l2 : l1;
        long base = (long)(b * SS + grow) * 64;
        float cnt = (float)(SS - 1 - grow);
        float e = 1.f, em = 0.f;
        if (cnt > 0.f) {
            float mn = fmaxf(mm, 0.f);
            e  = ex2(mm - mn);
            em = ex2(-mn);
            ll = ll * e + cnt * em;
        }
        float inv = 1.0f / ll;
#pragma unroll
        for (int nd = 0; nd < 16; ++nd) {
            float o0 = acc[nd][2 * h + 0];
            float o1 = acc[nd][2 * h + 1];
            if (cnt > 0.f) {
                float2 sv = SV2[base + nd * 4 + m_];
                o0 = o0 * e + em * sv.x;
                o1 = o1 * e + em * sv.y;
            }
            O2[base + nd * 4 + m_] = make_float2(o0 * inv, o1 * inv);
        }
    }
}

// ---------------------------------------------------------------------------
extern "C" void kernel_launch(void* const* d_in, const int* in_sizes, int n_in,
                              void* d_out, int out_size) {
    const float* Q = (const float*)d_in[0];
    const float* K = (const float*)d_in[1];
    const float* V = (const float*)d_in[2];
    float*       O = (float*)d_out;

    cudaFuncSetAttribute(flash_kernel,
                         cudaFuncAttributeMaxDynamicSharedMemorySize, SMEM_BYTES);

    chunk_sum_kernel<<<dim3(NCH, SB), 128>>>(V);
    suffix_kernel   <<<dim3(NCH, SB), 128>>>(V);
    // batch on x, qtile on y (heavy-first LPT order)
    flash_kernel    <<<dim3(SB, SS / BM), 256, SMEM_BYTES>>>(Q, K, V, O);
}